// round 10
// baseline (speedup 1.0000x reference)
#include <cuda_runtime.h>

#define D_MODEL 1024
#define SEQ     1024
#define BATCH   8
#define HEADS   16
#define DKH     64
#define LAYERS  4
#define MROWS   (BATCH*SEQ)   // 8192

// ---------------- scratch (device globals; no allocations) ----------------
__device__ float g_x [MROWS*D_MODEL];
__device__ float g_q [MROWS*D_MODEL];
__device__ float g_k [MROWS*D_MODEL];
__device__ float g_v [MROWS*D_MODEL];
__device__ float g_o [MROWS*D_MODEL];   // attention out; reused as FFN hidden
__device__ float g_t [MROWS*D_MODEL];   // residual sums (LN input)
__device__ float g_r0[MROWS*D_MODEL];
__device__ float g_part[BATCH*128*2];
__device__ float g_stats[BATCH*2];      // mean, rstd per batch sample

// ---------------- positional encoding + input add ----------------
__global__ void posenc_kernel(const float* __restrict__ X, float* __restrict__ out)
{
    int idx = blockIdx.x * 256 + threadIdx.x;     // 0 .. 8M-1
    int d = idx & (D_MODEL - 1);
    int s = (idx >> 10) & (SEQ - 1);
    float e   = (float)(d & ~1) * (1.0f / (float)D_MODEL);   // 2*(d/2)/D
    float inv = expf(-6.9077552789821368f * e);               // 1000^-e
    float ang = (float)s * inv;
    float pe  = (d & 1) ? cosf(ang) : sinf(ang);
    out[idx] = X[idx] + pe;
}

// ---------------- generic NT SGEMM: C[m,n] = dot(A[m,:], W[n,:]) ----------------
// M=8192, N=1024, K=1024. Optional: LN applied to A on load, bias, relu, residual.
template<bool LNA, bool BIAS, bool RELU, bool RES>
__global__ __launch_bounds__(256, 2) void gemm_nt(
    const float* __restrict__ A, const float* __restrict__ W,
    const float* __restrict__ bias, const float* __restrict__ res,
    const float* __restrict__ stats, float* __restrict__ C)
{
    const int K = 1024, N = 1024;
    __shared__ float As[16][128];
    __shared__ float Ws[16][128];

    int tid = threadIdx.x;
    int mt = blockIdx.y, nt = blockIdx.x;
    const float* Ab = A + mt * 128 * K;
    const float* Wb = W + nt * 128 * K;

    float mean = 0.f, rstd = 1.f;
    if (LNA) { int b = (mt * 128) >> 10; mean = stats[2*b]; rstd = stats[2*b + 1]; }

    float acc[8][8];
    #pragma unroll
    for (int i = 0; i < 8; i++)
        #pragma unroll
        for (int j = 0; j < 8; j++) acc[i][j] = 0.f;

    int lr = tid >> 2;            // 0..63 (row within half-tile)
    int lk = (tid & 3) << 2;      // k-quad start: 0,4,8,12

    for (int kt = 0; kt < K; kt += 16) {
        __syncthreads();
        #pragma unroll
        for (int i = 0; i < 2; i++) {
            int r = lr + i * 64;
            float4 va = *(const float4*)(Ab + r * K + kt + lk);
            if (LNA) {
                va.x = (va.x - mean) * rstd; va.y = (va.y - mean) * rstd;
                va.z = (va.z - mean) * rstd; va.w = (va.w - mean) * rstd;
            }
            As[lk+0][r] = va.x; As[lk+1][r] = va.y;
            As[lk+2][r] = va.z; As[lk+3][r] = va.w;
            float4 vw = *(const float4*)(Wb + r * K + kt + lk);
            Ws[lk+0][r] = vw.x; Ws[lk+1][r] = vw.y;
            Ws[lk+2][r] = vw.z; Ws[lk+3][r] = vw.w;
        }
        __syncthreads();
        #pragma unroll
        for (int k = 0; k < 16; k++) {
            float a[8], b[8];
            *(float4*)&a[0] = *(const float4*)&As[k][(tid >> 4) * 8];
            *(float4*)&a[4] = *(const float4*)&As[k][(tid >> 4) * 8 + 4];
            *(float4*)&b[0] = *(const float4*)&Ws[k][(tid & 15) * 8];
            *(float4*)&b[4] = *(const float4*)&Ws[k][(tid & 15) * 8 + 4];
            #pragma unroll
            for (int i = 0; i < 8; i++)
                #pragma unroll
                for (int j = 0; j < 8; j++)
                    acc[i][j] += a[i] * b[j];
        }
    }

    int row0 = mt * 128 + (tid >> 4) * 8;
    int col0 = nt * 128 + (tid & 15) * 8;
    #pragma unroll
    for (int i = 0; i < 8; i++) {
        float v[8];
        #pragma unroll
        for (int j = 0; j < 8; j++) {
            float x = acc[i][j];
            if (BIAS) x += bias[col0 + j];
            if (RES)  x += res[(row0 + i) * N + col0 + j];
            if (RELU) x = fmaxf(x, 0.f);
            v[j] = x;
        }
        float4* cp = (float4*)(C + (row0 + i) * N + col0);
        cp[0] = make_float4(v[0], v[1], v[2], v[3]);
        cp[1] = make_float4(v[4], v[5], v[6], v[7]);
    }
}

// ---------------- flash attention (fp32, online softmax) ----------------
// grid: (S/64, H, B); 256 threads; thread = (query row qr = tid>>2, col-group g = tid&3)
__global__ __launch_bounds__(256) void attn_kernel(
    const float* __restrict__ Q, const float* __restrict__ Kg,
    const float* __restrict__ Vg, float* __restrict__ O)
{
    __shared__ float Qs [64][68];
    __shared__ float KVs[64][68];
    int qt = blockIdx.x, h = blockIdx.y, b = blockIdx.z;
    int tid = threadIdx.x;
    int qr = tid >> 2;
    int g  = tid & 3;
    int base = (b * SEQ) * D_MODEL + h * DKH;

    #pragma unroll
    for (int i = 0; i < 4; i++) {
        int s = tid + i * 256;
        int r = s >> 4, kq = (s & 15) << 2;
        *(float4*)&Qs[r][kq] = *(const float4*)(Q + base + (qt * 64 + r) * D_MODEL + kq);
    }

    float m = -1e30f, l = 0.f;
    float acc[64];
    #pragma unroll
    for (int i = 0; i < 64; i++) acc[i] = 0.f;

    for (int t = 0; t < 16; t++) {
        __syncthreads();
        #pragma unroll
        for (int i = 0; i < 4; i++) {
            int s = tid + i * 256;
            int r = s >> 4, kq = (s & 15) << 2;
            *(float4*)&KVs[r][kq] = *(const float4*)(Kg + base + (t * 64 + r) * D_MODEL + kq);
        }
        __syncthreads();

        float sc[16];
        #pragma unroll
        for (int i = 0; i < 16; i++) sc[i] = 0.f;
        #pragma unroll
        for (int k4 = 0; k4 < 16; k4++) {
            float4 qv = *(const float4*)&Qs[qr][k4 * 4];
            #pragma unroll
            for (int c16 = 0; c16 < 16; c16++) {
                float4 kv = *(const float4*)&KVs[g + c16 * 4][k4 * 4];
                sc[c16] += qv.x * kv.x + qv.y * kv.y + qv.z * kv.z + qv.w * kv.w;
            }
        }

        float tmax = -1e30f;
        #pragma unroll
        for (int i = 0; i < 16; i++) { sc[i] *= 0.125f; tmax = fmaxf(tmax, sc[i]); }
        tmax = fmaxf(tmax, __shfl_xor_sync(0xffffffffu, tmax, 1));
        tmax = fmaxf(tmax, __shfl_xor_sync(0xffffffffu, tmax, 2));
        float mnew = fmaxf(m, tmax);
        float corr = __expf(m - mnew);
        float lsum = 0.f;
        #pragma unroll
        for (int i = 0; i < 16; i++) { sc[i] = __expf(sc[i] - mnew); lsum += sc[i]; }
        lsum += __shfl_xor_sync(0xffffffffu, lsum, 1);
        lsum += __shfl_xor_sync(0xffffffffu, lsum, 2);
        l = l * corr + lsum;
        m = mnew;
        #pragma unroll
        for (int i = 0; i < 64; i++) acc[i] *= corr;

        __syncthreads();
        #pragma unroll
        for (int i = 0; i < 4; i++) {
            int s = tid + i * 256;
            int r = s >> 4, kq = (s & 15) << 2;
            *(float4*)&KVs[r][kq] = *(const float4*)(Vg + base + (t * 64 + r) * D_MODEL + kq);
        }
        __syncthreads();

        #pragma unroll
        for (int c16 = 0; c16 < 16; c16++) {
            float p = sc[c16];
            int c = g + c16 * 4;
            #pragma unroll
            for (int d4 = 0; d4 < 16; d4++) {
                float4 v = *(const float4*)&KVs[c][d4 * 4];
                acc[d4*4+0] += p * v.x;
                acc[d4*4+1] += p * v.y;
                acc[d4*4+2] += p * v.z;
                acc[d4*4+3] += p * v.w;
            }
        }
    }

    float invl = 1.f / l;
    float* orow = O + base + (qt * 64 + qr) * D_MODEL;
    #pragma unroll
    for (int dk = 0; dk < 64; dk++) {
        float v = acc[dk];
        v += __shfl_xor_sync(0xffffffffu, v, 1);
        v += __shfl_xor_sync(0xffffffffu, v, 2);
        if ((dk >> 4) == g) orow[dk] = v * invl;
    }
}

// ---------------- LayerNorm statistics (deterministic 2-stage) ----------------
__global__ void red_partial(const float* __restrict__ t, float* __restrict__ part)
{
    int b = blockIdx.y, ch = blockIdx.x;
    const float4* p = (const float4*)(t + (b << 20) + (ch << 13));
    float s = 0.f, sq = 0.f;
    for (int i = threadIdx.x; i < 2048; i += 256) {
        float4 v = p[i];
        s  += v.x + v.y + v.z + v.w;
        sq += v.x*v.x + v.y*v.y + v.z*v.z + v.w*v.w;
    }
    __shared__ float ss[256], sqs[256];
    ss[threadIdx.x] = s; sqs[threadIdx.x] = sq;
    __syncthreads();
    for (int st = 128; st > 0; st >>= 1) {
        if (threadIdx.x < st) {
            ss[threadIdx.x]  += ss[threadIdx.x + st];
            sqs[threadIdx.x] += sqs[threadIdx.x + st];
        }
        __syncthreads();
    }
    if (threadIdx.x == 0) {
        part[(b * 128 + ch) * 2]     = ss[0];
        part[(b * 128 + ch) * 2 + 1] = sqs[0];
    }
}

__global__ void red_final(const float* __restrict__ part, float* __restrict__ stats)
{
    int b = blockIdx.x;
    int tid = threadIdx.x;   // 128 threads
    __shared__ float ss[128], sqs[128];
    ss[tid]  = part[(b * 128 + tid) * 2];
    sqs[tid] = part[(b * 128 + tid) * 2 + 1];
    __syncthreads();
    for (int st = 64; st > 0; st >>= 1) {
        if (tid < st) { ss[tid] += ss[tid + st]; sqs[tid] += sqs[tid + st]; }
        __syncthreads();
    }
    if (tid == 0) {
        float n = (float)(SEQ * D_MODEL);
        float mean = ss[0] / n;
        float var  = sqs[0] / n - mean * mean;
        stats[2 * b]     = mean;
        stats[2 * b + 1] = rsqrtf(var + 1e-5f);
    }
}

// ---------------- driver ----------------
extern "C" void kernel_launch(void* const* d_in, const int* in_sizes, int n_in,
                              void* d_out, int out_size)
{
    const float* X    = (const float*)d_in[0];
    const float* Wq   = (const float*)d_in[1];
    const float* Wk   = (const float*)d_in[2];
    const float* Wv   = (const float*)d_in[3];
    const float* W0   = (const float*)d_in[4];
    const float* Wrw  = (const float*)d_in[5];
    const float* Wrb  = (const float*)d_in[6];
    const float* Wf0w = (const float*)d_in[7];
    const float* Wf0b = (const float*)d_in[8];
    const float* Wf1w = (const float*)d_in[9];
    const float* Wf1b = (const float*)d_in[10];
    float* out = (float*)d_out;

    float *bx, *bq, *bk, *bv, *bo, *bt, *br, *bpart, *bstats;
    cudaGetSymbolAddress((void**)&bx,     g_x);
    cudaGetSymbolAddress((void**)&bq,     g_q);
    cudaGetSymbolAddress((void**)&bk,     g_k);
    cudaGetSymbolAddress((void**)&bv,     g_v);
    cudaGetSymbolAddress((void**)&bo,     g_o);
    cudaGetSymbolAddress((void**)&bt,     g_t);
    cudaGetSymbolAddress((void**)&br,     g_r0);
    cudaGetSymbolAddress((void**)&bpart,  g_part);
    cudaGetSymbolAddress((void**)&bstats, g_stats);

    dim3 gg(8, 64);                 // (N/128, M/128)
    dim3 ga(16, 16, 8);             // (S/64, H, B)
    dim3 gr(128, 8);                // (chunks, B)

    posenc_kernel<<<(MROWS * D_MODEL) / 256, 256>>>(X, bx);

    for (int l = 0; l < LAYERS; l++) {
        size_t mm = (size_t)l * D_MODEL * D_MODEL;
        const float* wq   = Wq   + mm;
        const float* wk   = Wk   + mm;
        const float* wv   = Wv   + mm;
        const float* w0   = W0   + mm;
        const float* wrw  = Wrw  + mm;
        const float* wrb  = Wrb  + (size_t)l * D_MODEL;
        const float* wf0w = Wf0w + mm;
        const float* wf0b = Wf0b + (size_t)l * D_MODEL;
        const float* wf1w = Wf1w + mm;
        const float* wf1b = Wf1b + (size_t)l * D_MODEL;

        // Q, K, V projections
        gemm_nt<false,false,false,false><<<gg, 256>>>(bx, wq, nullptr, nullptr, nullptr, bq);
        gemm_nt<false,false,false,false><<<gg, 256>>>(bx, wk, nullptr, nullptr, nullptr, bk);
        gemm_nt<false,false,false,false><<<gg, 256>>>(bx, wv, nullptr, nullptr, nullptr, bv);
        // attention
        attn_kernel<<<ga, 256>>>(bq, bk, bv, bo);
        // t = x + O @ W0^T
        gemm_nt<false,false,false,true ><<<gg, 256>>>(bo, w0, nullptr, bx, nullptr, bt);
        // LN stats of t
        red_partial<<<gr, 256>>>(bt, bpart);
        red_final<<<8, 128>>>(bpart, bstats);
        // r0 = LN(t) @ Wr^T + br   (LN fused into A-load)
        gemm_nt<true ,true ,false,false><<<gg, 256>>>(bt, wrw, wrb, nullptr, bstats, br);
        // h = relu(r0 @ Wf0^T + b0)   (stored in bo)
        gemm_nt<false,true ,true ,false><<<gg, 256>>>(br, wf0w, wf0b, nullptr, nullptr, bo);
        // t = h @ Wf1^T + b1 + r0
        gemm_nt<false,true ,false,true ><<<gg, 256>>>(bo, wf1w, wf1b, br, nullptr, bt);
        // LN stats of t
        red_partial<<<gr, 256>>>(bt, bpart);
        red_final<<<8, 128>>>(bpart, bstats);
        // x = LN(t) @ Wr^T + br
        float* dst = (l == LAYERS - 1) ? out : bx;
        gemm_nt<true ,true ,false,false><<<gg, 256>>>(bt, wrw, wrb, nullptr, bstats, dst);
    }
}

// round 11
// speedup vs baseline: 1.0005x; 1.0005x over previous
#include <cuda_runtime.h>

#define D_MODEL 1024
#define SEQ     1024
#define BATCH   8
#define HEADS   16
#define DKH     64
#define LAYERS  4
#define MROWS   (BATCH*SEQ)   // 8192

// ---------------- scratch (device globals; no allocations) ----------------
__device__ float g_x [MROWS*D_MODEL];
__device__ float g_q [MROWS*D_MODEL];
__device__ float g_k [MROWS*D_MODEL];
__device__ float g_v [MROWS*D_MODEL];
__device__ float g_o [MROWS*D_MODEL];   // attention out; reused as FFN hidden
__device__ float g_t [MROWS*D_MODEL];   // residual sums (LN input)
__device__ float g_r0[MROWS*D_MODEL];
__device__ float g_part[BATCH*128*2];
__device__ float g_stats[BATCH*2];      // mean, rstd per batch sample

// ---------------- positional encoding + input add ----------------
__global__ void posenc_kernel(const float* __restrict__ X, float* __restrict__ out)
{
    int idx = blockIdx.x * 256 + threadIdx.x;     // 0 .. 8M-1
    int d = idx & (D_MODEL - 1);
    int s = (idx >> 10) & (SEQ - 1);
    float e   = (float)(d & ~1) * (1.0f / (float)D_MODEL);   // 2*(d/2)/D
    float inv = expf(-6.9077552789821368f * e);               // 1000^-e
    float ang = (float)s * inv;
    float pe  = (d & 1) ? cosf(ang) : sinf(ang);
    out[idx] = X[idx] + pe;
}

// ---------------- generic NT SGEMM: C[m,n] = dot(A[m,:], W[n,:]) ----------------
// M=8192, N=1024, K=1024. Optional: LN applied to A on load, bias, relu, residual.
template<bool LNA, bool BIAS, bool RELU, bool RES>
__global__ __launch_bounds__(256, 2) void gemm_nt(
    const float* __restrict__ A, const float* __restrict__ W,
    const float* __restrict__ bias, const float* __restrict__ res,
    const float* __restrict__ stats, float* __restrict__ C)
{
    const int K = 1024, N = 1024;
    __shared__ float As[16][128];
    __shared__ float Ws[16][128];

    int tid = threadIdx.x;
    int mt = blockIdx.y, nt = blockIdx.x;
    const float* Ab = A + mt * 128 * K;
    const float* Wb = W + nt * 128 * K;

    float mean = 0.f, rstd = 1.f;
    if (LNA) { int b = (mt * 128) >> 10; mean = stats[2*b]; rstd = stats[2*b + 1]; }

    float acc[8][8];
    #pragma unroll
    for (int i = 0; i < 8; i++)
        #pragma unroll
        for (int j = 0; j < 8; j++) acc[i][j] = 0.f;

    int lr = tid >> 2;            // 0..63 (row within half-tile)
    int lk = (tid & 3) << 2;      // k-quad start: 0,4,8,12

    for (int kt = 0; kt < K; kt += 16) {
        __syncthreads();
        #pragma unroll
        for (int i = 0; i < 2; i++) {
            int r = lr + i * 64;
            float4 va = *(const float4*)(Ab + r * K + kt + lk);
            if (LNA) {
                va.x = (va.x - mean) * rstd; va.y = (va.y - mean) * rstd;
                va.z = (va.z - mean) * rstd; va.w = (va.w - mean) * rstd;
            }
            As[lk+0][r] = va.x; As[lk+1][r] = va.y;
            As[lk+2][r] = va.z; As[lk+3][r] = va.w;
            float4 vw = *(const float4*)(Wb + r * K + kt + lk);
            Ws[lk+0][r] = vw.x; Ws[lk+1][r] = vw.y;
            Ws[lk+2][r] = vw.z; Ws[lk+3][r] = vw.w;
        }
        __syncthreads();
        #pragma unroll
        for (int k = 0; k < 16; k++) {
            float a[8], b[8];
            *(float4*)&a[0] = *(const float4*)&As[k][(tid >> 4) * 8];
            *(float4*)&a[4] = *(const float4*)&As[k][(tid >> 4) * 8 + 4];
            *(float4*)&b[0] = *(const float4*)&Ws[k][(tid & 15) * 8];
            *(float4*)&b[4] = *(const float4*)&Ws[k][(tid & 15) * 8 + 4];
            #pragma unroll
            for (int i = 0; i < 8; i++)
                #pragma unroll
                for (int j = 0; j < 8; j++)
                    acc[i][j] += a[i] * b[j];
        }
    }

    int row0 = mt * 128 + (tid >> 4) * 8;
    int col0 = nt * 128 + (tid & 15) * 8;
    #pragma unroll
    for (int i = 0; i < 8; i++) {
        float v[8];
        #pragma unroll
        for (int j = 0; j < 8; j++) {
            float x = acc[i][j];
            if (BIAS) x += bias[col0 + j];
            if (RES)  x += res[(row0 + i) * N + col0 + j];
            if (RELU) x = fmaxf(x, 0.f);
            v[j] = x;
        }
        float4* cp = (float4*)(C + (row0 + i) * N + col0);
        cp[0] = make_float4(v[0], v[1], v[2], v[3]);
        cp[1] = make_float4(v[4], v[5], v[6], v[7]);
    }
}

// ---------------- flash attention (fp32, online softmax) ----------------
// grid: (S/64, H, B); 256 threads; thread = (query row qr = tid>>2, col-group g = tid&3)
__global__ __launch_bounds__(256) void attn_kernel(
    const float* __restrict__ Q, const float* __restrict__ Kg,
    const float* __restrict__ Vg, float* __restrict__ O)
{
    __shared__ float Qs [64][68];
    __shared__ float KVs[64][68];
    int qt = blockIdx.x, h = blockIdx.y, b = blockIdx.z;
    int tid = threadIdx.x;
    int qr = tid >> 2;
    int g  = tid & 3;
    int base = (b * SEQ) * D_MODEL + h * DKH;

    #pragma unroll
    for (int i = 0; i < 4; i++) {
        int s = tid + i * 256;
        int r = s >> 4, kq = (s & 15) << 2;
        *(float4*)&Qs[r][kq] = *(const float4*)(Q + base + (qt * 64 + r) * D_MODEL + kq);
    }

    float m = -1e30f, l = 0.f;
    float acc[64];
    #pragma unroll
    for (int i = 0; i < 64; i++) acc[i] = 0.f;

    for (int t = 0; t < 16; t++) {
        __syncthreads();
        #pragma unroll
        for (int i = 0; i < 4; i++) {
            int s = tid + i * 256;
            int r = s >> 4, kq = (s & 15) << 2;
            *(float4*)&KVs[r][kq] = *(const float4*)(Kg + base + (t * 64 + r) * D_MODEL + kq);
        }
        __syncthreads();

        float sc[16];
        #pragma unroll
        for (int i = 0; i < 16; i++) sc[i] = 0.f;
        #pragma unroll
        for (int k4 = 0; k4 < 16; k4++) {
            float4 qv = *(const float4*)&Qs[qr][k4 * 4];
            #pragma unroll
            for (int c16 = 0; c16 < 16; c16++) {
                float4 kv = *(const float4*)&KVs[g + c16 * 4][k4 * 4];
                sc[c16] += qv.x * kv.x + qv.y * kv.y + qv.z * kv.z + qv.w * kv.w;
            }
        }

        float tmax = -1e30f;
        #pragma unroll
        for (int i = 0; i < 16; i++) { sc[i] *= 0.125f; tmax = fmaxf(tmax, sc[i]); }
        tmax = fmaxf(tmax, __shfl_xor_sync(0xffffffffu, tmax, 1));
        tmax = fmaxf(tmax, __shfl_xor_sync(0xffffffffu, tmax, 2));
        float mnew = fmaxf(m, tmax);
        float corr = __expf(m - mnew);
        float lsum = 0.f;
        #pragma unroll
        for (int i = 0; i < 16; i++) { sc[i] = __expf(sc[i] - mnew); lsum += sc[i]; }
        lsum += __shfl_xor_sync(0xffffffffu, lsum, 1);
        lsum += __shfl_xor_sync(0xffffffffu, lsum, 2);
        l = l * corr + lsum;
        m = mnew;
        #pragma unroll
        for (int i = 0; i < 64; i++) acc[i] *= corr;

        __syncthreads();
        #pragma unroll
        for (int i = 0; i < 4; i++) {
            int s = tid + i * 256;
            int r = s >> 4, kq = (s & 15) << 2;
            *(float4*)&KVs[r][kq] = *(const float4*)(Vg + base + (t * 64 + r) * D_MODEL + kq);
        }
        __syncthreads();

        #pragma unroll
        for (int c16 = 0; c16 < 16; c16++) {
            float p = sc[c16];
            int c = g + c16 * 4;
            #pragma unroll
            for (int d4 = 0; d4 < 16; d4++) {
                float4 v = *(const float4*)&KVs[c][d4 * 4];
                acc[d4*4+0] += p * v.x;
                acc[d4*4+1] += p * v.y;
                acc[d4*4+2] += p * v.z;
                acc[d4*4+3] += p * v.w;
            }
        }
    }

    float invl = 1.f / l;
    float* orow = O + base + (qt * 64 + qr) * D_MODEL;
    #pragma unroll
    for (int dk = 0; dk < 64; dk++) {
        float v = acc[dk];
        v += __shfl_xor_sync(0xffffffffu, v, 1);
        v += __shfl_xor_sync(0xffffffffu, v, 2);
        if ((dk >> 4) == g) orow[dk] = v * invl;
    }
}

// ---------------- LayerNorm statistics (deterministic 2-stage) ----------------
__global__ void red_partial(const float* __restrict__ t, float* __restrict__ part)
{
    int b = blockIdx.y, ch = blockIdx.x;
    const float4* p = (const float4*)(t + (b << 20) + (ch << 13));
    float s = 0.f, sq = 0.f;
    for (int i = threadIdx.x; i < 2048; i += 256) {
        float4 v = p[i];
        s  += v.x + v.y + v.z + v.w;
        sq += v.x*v.x + v.y*v.y + v.z*v.z + v.w*v.w;
    }
    __shared__ float ss[256], sqs[256];
    ss[threadIdx.x] = s; sqs[threadIdx.x] = sq;
    __syncthreads();
    for (int st = 128; st > 0; st >>= 1) {
        if (threadIdx.x < st) {
            ss[threadIdx.x]  += ss[threadIdx.x + st];
            sqs[threadIdx.x] += sqs[threadIdx.x + st];
        }
        __syncthreads();
    }
    if (threadIdx.x == 0) {
        part[(b * 128 + ch) * 2]     = ss[0];
        part[(b * 128 + ch) * 2 + 1] = sqs[0];
    }
}

__global__ void red_final(const float* __restrict__ part, float* __restrict__ stats)
{
    int b = blockIdx.x;
    int tid = threadIdx.x;   // 128 threads
    __shared__ float ss[128], sqs[128];
    ss[tid]  = part[(b * 128 + tid) * 2];
    sqs[tid] = part[(b * 128 + tid) * 2 + 1];
    __syncthreads();
    for (int st = 64; st > 0; st >>= 1) {
        if (tid < st) { ss[tid] += ss[tid + st]; sqs[tid] += sqs[tid + st]; }
        __syncthreads();
    }
    if (tid == 0) {
        float n = (float)(SEQ * D_MODEL);
        float mean = ss[0] / n;
        float var  = sqs[0] / n - mean * mean;
        stats[2 * b]     = mean;
        stats[2 * b + 1] = rsqrtf(var + 1e-5f);
    }
}

// ---------------- driver ----------------
extern "C" void kernel_launch(void* const* d_in, const int* in_sizes, int n_in,
                              void* d_out, int out_size)
{
    const float* X    = (const float*)d_in[0];
    const float* Wq   = (const float*)d_in[1];
    const float* Wk   = (const float*)d_in[2];
    const float* Wv   = (const float*)d_in[3];
    const float* W0   = (const float*)d_in[4];
    const float* Wrw  = (const float*)d_in[5];
    const float* Wrb  = (const float*)d_in[6];
    const float* Wf0w = (const float*)d_in[7];
    const float* Wf0b = (const float*)d_in[8];
    const float* Wf1w = (const float*)d_in[9];
    const float* Wf1b = (const float*)d_in[10];
    float* out = (float*)d_out;

    float *bx, *bq, *bk, *bv, *bo, *bt, *br, *bpart, *bstats;
    cudaGetSymbolAddress((void**)&bx,     g_x);
    cudaGetSymbolAddress((void**)&bq,     g_q);
    cudaGetSymbolAddress((void**)&bk,     g_k);
    cudaGetSymbolAddress((void**)&bv,     g_v);
    cudaGetSymbolAddress((void**)&bo,     g_o);
    cudaGetSymbolAddress((void**)&bt,     g_t);
    cudaGetSymbolAddress((void**)&br,     g_r0);
    cudaGetSymbolAddress((void**)&bpart,  g_part);
    cudaGetSymbolAddress((void**)&bstats, g_stats);

    dim3 gg(8, 64);                 // (N/128, M/128)
    dim3 ga(16, 16, 8);             // (S/64, H, B)
    dim3 gr(128, 8);                // (chunks, B)

    posenc_kernel<<<(MROWS * D_MODEL) / 256, 256>>>(X, bx);

    for (int l = 0; l < LAYERS; l++) {
        size_t mm = (size_t)l * D_MODEL * D_MODEL;
        const float* wq   = Wq   + mm;
        const float* wk   = Wk   + mm;
        const float* wv   = Wv   + mm;
        const float* w0   = W0   + mm;
        const float* wrw  = Wrw  + mm;
        const float* wrb  = Wrb  + (size_t)l * D_MODEL;
        const float* wf0w = Wf0w + mm;
        const float* wf0b = Wf0b + (size_t)l * D_MODEL;
        const float* wf1w = Wf1w + mm;
        const float* wf1b = Wf1b + (size_t)l * D_MODEL;

        // Q, K, V projections
        gemm_nt<false,false,false,false><<<gg, 256>>>(bx, wq, nullptr, nullptr, nullptr, bq);
        gemm_nt<false,false,false,false><<<gg, 256>>>(bx, wk, nullptr, nullptr, nullptr, bk);
        gemm_nt<false,false,false,false><<<gg, 256>>>(bx, wv, nullptr, nullptr, nullptr, bv);
        // attention
        attn_kernel<<<ga, 256>>>(bq, bk, bv, bo);
        // t = x + O @ W0^T
        gemm_nt<false,false,false,true ><<<gg, 256>>>(bo, w0, nullptr, bx, nullptr, bt);
        // LN stats of t
        red_partial<<<gr, 256>>>(bt, bpart);
        red_final<<<8, 128>>>(bpart, bstats);
        // r0 = LN(t) @ Wr^T + br   (LN fused into A-load)
        gemm_nt<true ,true ,false,false><<<gg, 256>>>(bt, wrw, wrb, nullptr, bstats, br);
        // h = relu(r0 @ Wf0^T + b0)   (stored in bo)
        gemm_nt<false,true ,true ,false><<<gg, 256>>>(br, wf0w, wf0b, nullptr, nullptr, bo);
        // t = h @ Wf1^T + b1 + r0
        gemm_nt<false,true ,false,true ><<<gg, 256>>>(bo, wf1w, wf1b, br, nullptr, bt);
        // LN stats of t
        red_partial<<<gr, 256>>>(bt, bpart);
        red_final<<<8, 128>>>(bpart, bstats);
        // x = LN(t) @ Wr^T + br
        float* dst = (l == LAYERS - 1) ? out : bx;
        gemm_nt<true ,true ,false,false><<<gg, 256>>>(bt, wrw, wrb, nullptr, bstats, dst);
    }
}

// round 12
// speedup vs baseline: 1.0018x; 1.0014x over previous
#include <cuda_runtime.h>

#define D_MODEL 1024
#define SEQ     1024
#define BATCH   8
#define HEADS   16
#define DKH     64
#define LAYERS  4
#define MROWS   (BATCH*SEQ)   // 8192

// ---------------- scratch (device globals; no allocations) ----------------
__device__ float g_x [MROWS*D_MODEL];
__device__ float g_q [MROWS*D_MODEL];
__device__ float g_k [MROWS*D_MODEL];
__device__ float g_v [MROWS*D_MODEL];
__device__ float g_o [MROWS*D_MODEL];   // attention out; reused as FFN hidden
__device__ float g_t [MROWS*D_MODEL];   // residual sums (LN input)
__device__ float g_r0[MROWS*D_MODEL];
__device__ float g_part[BATCH*128*2];
__device__ float g_stats[BATCH*2];      // mean, rstd per batch sample

// ---------------- positional encoding + input add ----------------
__global__ void posenc_kernel(const float* __restrict__ X, float* __restrict__ out)
{
    int idx = blockIdx.x * 256 + threadIdx.x;     // 0 .. 8M-1
    int d = idx & (D_MODEL - 1);
    int s = (idx >> 10) & (SEQ - 1);
    float e   = (float)(d & ~1) * (1.0f / (float)D_MODEL);   // 2*(d/2)/D
    float inv = expf(-6.9077552789821368f * e);               // 1000^-e
    float ang = (float)s * inv;
    float pe  = (d & 1) ? cosf(ang) : sinf(ang);
    out[idx] = X[idx] + pe;
}

// ---------------- generic NT SGEMM: C[m,n] = dot(A[m,:], W[n,:]) ----------------
// M=8192, N=1024, K=1024. Optional: LN applied to A on load, bias, relu, residual.
template<bool LNA, bool BIAS, bool RELU, bool RES>
__global__ __launch_bounds__(256, 2) void gemm_nt(
    const float* __restrict__ A, const float* __restrict__ W,
    const float* __restrict__ bias, const float* __restrict__ res,
    const float* __restrict__ stats, float* __restrict__ C)
{
    const int K = 1024, N = 1024;
    __shared__ float As[16][128];
    __shared__ float Ws[16][128];

    int tid = threadIdx.x;
    int mt = blockIdx.y, nt = blockIdx.x;
    const float* Ab = A + mt * 128 * K;
    const float* Wb = W + nt * 128 * K;

    float mean = 0.f, rstd = 1.f;
    if (LNA) { int b = (mt * 128) >> 10; mean = stats[2*b]; rstd = stats[2*b + 1]; }

    float acc[8][8];
    #pragma unroll
    for (int i = 0; i < 8; i++)
        #pragma unroll
        for (int j = 0; j < 8; j++) acc[i][j] = 0.f;

    int lr = tid >> 2;            // 0..63 (row within half-tile)
    int lk = (tid & 3) << 2;      // k-quad start: 0,4,8,12

    for (int kt = 0; kt < K; kt += 16) {
        __syncthreads();
        #pragma unroll
        for (int i = 0; i < 2; i++) {
            int r = lr + i * 64;
            float4 va = *(const float4*)(Ab + r * K + kt + lk);
            if (LNA) {
                va.x = (va.x - mean) * rstd; va.y = (va.y - mean) * rstd;
                va.z = (va.z - mean) * rstd; va.w = (va.w - mean) * rstd;
            }
            As[lk+0][r] = va.x; As[lk+1][r] = va.y;
            As[lk+2][r] = va.z; As[lk+3][r] = va.w;
            float4 vw = *(const float4*)(Wb + r * K + kt + lk);
            Ws[lk+0][r] = vw.x; Ws[lk+1][r] = vw.y;
            Ws[lk+2][r] = vw.z; Ws[lk+3][r] = vw.w;
        }
        __syncthreads();
        #pragma unroll
        for (int k = 0; k < 16; k++) {
            float a[8], b[8];
            *(float4*)&a[0] = *(const float4*)&As[k][(tid >> 4) * 8];
            *(float4*)&a[4] = *(const float4*)&As[k][(tid >> 4) * 8 + 4];
            *(float4*)&b[0] = *(const float4*)&Ws[k][(tid & 15) * 8];
            *(float4*)&b[4] = *(const float4*)&Ws[k][(tid & 15) * 8 + 4];
            #pragma unroll
            for (int i = 0; i < 8; i++)
                #pragma unroll
                for (int j = 0; j < 8; j++)
                    acc[i][j] += a[i] * b[j];
        }
    }

    int row0 = mt * 128 + (tid >> 4) * 8;
    int col0 = nt * 128 + (tid & 15) * 8;
    #pragma unroll
    for (int i = 0; i < 8; i++) {
        float v[8];
        #pragma unroll
        for (int j = 0; j < 8; j++) {
            float x = acc[i][j];
            if (BIAS) x += bias[col0 + j];
            if (RES)  x += res[(row0 + i) * N + col0 + j];
            if (RELU) x = fmaxf(x, 0.f);
            v[j] = x;
        }
        float4* cp = (float4*)(C + (row0 + i) * N + col0);
        cp[0] = make_float4(v[0], v[1], v[2], v[3]);
        cp[1] = make_float4(v[4], v[5], v[6], v[7]);
    }
}

// ---------------- flash attention (fp32, online softmax) ----------------
// grid: (S/64, H, B); 256 threads; thread = (query row qr = tid>>2, col-group g = tid&3)
__global__ __launch_bounds__(256) void attn_kernel(
    const float* __restrict__ Q, const float* __restrict__ Kg,
    const float* __restrict__ Vg, float* __restrict__ O)
{
    __shared__ float Qs [64][68];
    __shared__ float KVs[64][68];
    int qt = blockIdx.x, h = blockIdx.y, b = blockIdx.z;
    int tid = threadIdx.x;
    int qr = tid >> 2;
    int g  = tid & 3;
    int base = (b * SEQ) * D_MODEL + h * DKH;

    #pragma unroll
    for (int i = 0; i < 4; i++) {
        int s = tid + i * 256;
        int r = s >> 4, kq = (s & 15) << 2;
        *(float4*)&Qs[r][kq] = *(const float4*)(Q + base + (qt * 64 + r) * D_MODEL + kq);
    }

    float m = -1e30f, l = 0.f;
    float acc[64];
    #pragma unroll
    for (int i = 0; i < 64; i++) acc[i] = 0.f;

    for (int t = 0; t < 16; t++) {
        __syncthreads();
        #pragma unroll
        for (int i = 0; i < 4; i++) {
            int s = tid + i * 256;
            int r = s >> 4, kq = (s & 15) << 2;
            *(float4*)&KVs[r][kq] = *(const float4*)(Kg + base + (t * 64 + r) * D_MODEL + kq);
        }
        __syncthreads();

        float sc[16];
        #pragma unroll
        for (int i = 0; i < 16; i++) sc[i] = 0.f;
        #pragma unroll
        for (int k4 = 0; k4 < 16; k4++) {
            float4 qv = *(const float4*)&Qs[qr][k4 * 4];
            #pragma unroll
            for (int c16 = 0; c16 < 16; c16++) {
                float4 kv = *(const float4*)&KVs[g + c16 * 4][k4 * 4];
                sc[c16] += qv.x * kv.x + qv.y * kv.y + qv.z * kv.z + qv.w * kv.w;
            }
        }

        float tmax = -1e30f;
        #pragma unroll
        for (int i = 0; i < 16; i++) { sc[i] *= 0.125f; tmax = fmaxf(tmax, sc[i]); }
        tmax = fmaxf(tmax, __shfl_xor_sync(0xffffffffu, tmax, 1));
        tmax = fmaxf(tmax, __shfl_xor_sync(0xffffffffu, tmax, 2));
        float mnew = fmaxf(m, tmax);
        float corr = __expf(m - mnew);
        float lsum = 0.f;
        #pragma unroll
        for (int i = 0; i < 16; i++) { sc[i] = __expf(sc[i] - mnew); lsum += sc[i]; }
        lsum += __shfl_xor_sync(0xffffffffu, lsum, 1);
        lsum += __shfl_xor_sync(0xffffffffu, lsum, 2);
        l = l * corr + lsum;
        m = mnew;
        #pragma unroll
        for (int i = 0; i < 64; i++) acc[i] *= corr;

        __syncthreads();
        #pragma unroll
        for (int i = 0; i < 4; i++) {
            int s = tid + i * 256;
            int r = s >> 4, kq = (s & 15) << 2;
            *(float4*)&KVs[r][kq] = *(const float4*)(Vg + base + (t * 64 + r) * D_MODEL + kq);
        }
        __syncthreads();

        #pragma unroll
        for (int c16 = 0; c16 < 16; c16++) {
            float p = sc[c16];
            int c = g + c16 * 4;
            #pragma unroll
            for (int d4 = 0; d4 < 16; d4++) {
                float4 v = *(const float4*)&KVs[c][d4 * 4];
                acc[d4*4+0] += p * v.x;
                acc[d4*4+1] += p * v.y;
                acc[d4*4+2] += p * v.z;
                acc[d4*4+3] += p * v.w;
            }
        }
    }

    float invl = 1.f / l;
    float* orow = O + base + (qt * 64 + qr) * D_MODEL;
    #pragma unroll
    for (int dk = 0; dk < 64; dk++) {
        float v = acc[dk];
        v += __shfl_xor_sync(0xffffffffu, v, 1);
        v += __shfl_xor_sync(0xffffffffu, v, 2);
        if ((dk >> 4) == g) orow[dk] = v * invl;
    }
}

// ---------------- LayerNorm statistics (deterministic 2-stage) ----------------
__global__ void red_partial(const float* __restrict__ t, float* __restrict__ part)
{
    int b = blockIdx.y, ch = blockIdx.x;
    const float4* p = (const float4*)(t + (b << 20) + (ch << 13));
    float s = 0.f, sq = 0.f;
    for (int i = threadIdx.x; i < 2048; i += 256) {
        float4 v = p[i];
        s  += v.x + v.y + v.z + v.w;
        sq += v.x*v.x + v.y*v.y + v.z*v.z + v.w*v.w;
    }
    __shared__ float ss[256], sqs[256];
    ss[threadIdx.x] = s; sqs[threadIdx.x] = sq;
    __syncthreads();
    for (int st = 128; st > 0; st >>= 1) {
        if (threadIdx.x < st) {
            ss[threadIdx.x]  += ss[threadIdx.x + st];
            sqs[threadIdx.x] += sqs[threadIdx.x + st];
        }
        __syncthreads();
    }
    if (threadIdx.x == 0) {
        part[(b * 128 + ch) * 2]     = ss[0];
        part[(b * 128 + ch) * 2 + 1] = sqs[0];
    }
}

__global__ void red_final(const float* __restrict__ part, float* __restrict__ stats)
{
    int b = blockIdx.x;
    int tid = threadIdx.x;   // 128 threads
    __shared__ float ss[128], sqs[128];
    ss[tid]  = part[(b * 128 + tid) * 2];
    sqs[tid] = part[(b * 128 + tid) * 2 + 1];
    __syncthreads();
    for (int st = 64; st > 0; st >>= 1) {
        if (tid < st) { ss[tid] += ss[tid + st]; sqs[tid] += sqs[tid + st]; }
        __syncthreads();
    }
    if (tid == 0) {
        float n = (float)(SEQ * D_MODEL);
        float mean = ss[0] / n;
        float var  = sqs[0] / n - mean * mean;
        stats[2 * b]     = mean;
        stats[2 * b + 1] = rsqrtf(var + 1e-5f);
    }
}

// ---------------- driver ----------------
extern "C" void kernel_launch(void* const* d_in, const int* in_sizes, int n_in,
                              void* d_out, int out_size)
{
    const float* X    = (const float*)d_in[0];
    const float* Wq   = (const float*)d_in[1];
    const float* Wk   = (const float*)d_in[2];
    const float* Wv   = (const float*)d_in[3];
    const float* W0   = (const float*)d_in[4];
    const float* Wrw  = (const float*)d_in[5];
    const float* Wrb  = (const float*)d_in[6];
    const float* Wf0w = (const float*)d_in[7];
    const float* Wf0b = (const float*)d_in[8];
    const float* Wf1w = (const float*)d_in[9];
    const float* Wf1b = (const float*)d_in[10];
    float* out = (float*)d_out;

    float *bx, *bq, *bk, *bv, *bo, *bt, *br, *bpart, *bstats;
    cudaGetSymbolAddress((void**)&bx,     g_x);
    cudaGetSymbolAddress((void**)&bq,     g_q);
    cudaGetSymbolAddress((void**)&bk,     g_k);
    cudaGetSymbolAddress((void**)&bv,     g_v);
    cudaGetSymbolAddress((void**)&bo,     g_o);
    cudaGetSymbolAddress((void**)&bt,     g_t);
    cudaGetSymbolAddress((void**)&br,     g_r0);
    cudaGetSymbolAddress((void**)&bpart,  g_part);
    cudaGetSymbolAddress((void**)&bstats, g_stats);

    dim3 gg(8, 64);                 // (N/128, M/128)
    dim3 ga(16, 16, 8);             // (S/64, H, B)
    dim3 gr(128, 8);                // (chunks, B)

    posenc_kernel<<<(MROWS * D_MODEL) / 256, 256>>>(X, bx);

    for (int l = 0; l < LAYERS; l++) {
        size_t mm = (size_t)l * D_MODEL * D_MODEL;
        const float* wq   = Wq   + mm;
        const float* wk   = Wk   + mm;
        const float* wv   = Wv   + mm;
        const float* w0   = W0   + mm;
        const float* wrw  = Wrw  + mm;
        const float* wrb  = Wrb  + (size_t)l * D_MODEL;
        const float* wf0w = Wf0w + mm;
        const float* wf0b = Wf0b + (size_t)l * D_MODEL;
        const float* wf1w = Wf1w + mm;
        const float* wf1b = Wf1b + (size_t)l * D_MODEL;

        // Q, K, V projections
        gemm_nt<false,false,false,false><<<gg, 256>>>(bx, wq, nullptr, nullptr, nullptr, bq);
        gemm_nt<false,false,false,false><<<gg, 256>>>(bx, wk, nullptr, nullptr, nullptr, bk);
        gemm_nt<false,false,false,false><<<gg, 256>>>(bx, wv, nullptr, nullptr, nullptr, bv);
        // attention
        attn_kernel<<<ga, 256>>>(bq, bk, bv, bo);
        // t = x + O @ W0^T
        gemm_nt<false,false,false,true ><<<gg, 256>>>(bo, w0, nullptr, bx, nullptr, bt);
        // LN stats of t
        red_partial<<<gr, 256>>>(bt, bpart);
        red_final<<<8, 128>>>(bpart, bstats);
        // r0 = LN(t) @ Wr^T + br   (LN fused into A-load)
        gemm_nt<true ,true ,false,false><<<gg, 256>>>(bt, wrw, wrb, nullptr, bstats, br);
        // h = relu(r0 @ Wf0^T + b0)   (stored in bo)
        gemm_nt<false,true ,true ,false><<<gg, 256>>>(br, wf0w, wf0b, nullptr, nullptr, bo);
        // t = h @ Wf1^T + b1 + r0
        gemm_nt<false,true ,false,true ><<<gg, 256>>>(bo, wf1w, wf1b, br, nullptr, bt);
        // LN stats of t
        red_partial<<<gr, 256>>>(bt, bpart);
        red_final<<<8, 128>>>(bpart, bstats);
        // x = LN(t) @ Wr^T + br
        float* dst = (l == LAYERS - 1) ? out : bx;
        gemm_nt<true ,true ,false,false><<<gg, 256>>>(bt, wrw, wrb, nullptr, bstats, dst);
    }
}